// round 6
// baseline (speedup 1.0000x reference)
#include <cuda_runtime.h>

// ConstituencyMFVI: B=8, N=192, 3 iterations.
// One independent CTA per (b,i), 768 threads.
// The s_pair tile lives in REGISTERS: thread (jj = t%192, qd = t/192) holds
// row jj, k-quarter qd (48 floats = 12 float4). Loaded from gmem ONCE
// (iteration 1 fused into the load), reused for iterations 2-3.
// SMEM: only sig[2][192] + partial[768] (4.6 KB). Sig reads are warp-uniform
// broadcasts (192 % 32 == 0 -> qd uniform per warp).
// Mask terms (k==i, k==j) corrected analytically via prefetched scalars.

#define NDIM    192
#define QLEN    48        // k-quarter length
#define THREADS 768

__device__ __forceinline__ float sigmoidf_(float x) {
    return 1.0f / (1.0f + __expf(-x));
}

__global__ void __launch_bounds__(THREADS, 1)
mfvi_kernel(const float* __restrict__ s_span,
            const float* __restrict__ s_pair,
            float* __restrict__ out)
{
    __shared__ float sigA[NDIM];
    __shared__ float sigB[NDIM];
    __shared__ float partial[THREADS];

    const int bi  = blockIdx.x;            // b*192 + i
    const int i   = bi % NDIM;
    const int tid = threadIdx.x;
    const int jj  = tid % NDIM;            // row owned by this thread
    const int qd  = tid / NDIM;            // k-quarter index
    const int kb  = qd * QLEN;             // quarter base

    const bool active = (jj > i);

    const float* gbase = s_pair + (size_t)bi * (NDIM * NDIM);
    const float* grow  = gbase + (size_t)jj * NDIM;
    const float4* g4   = reinterpret_cast<const float4*>(grow + kb);

    // ---- Load this thread's 48 tile values into registers ----
    float4 r[12];
    float vi = 0.0f, vj = 0.0f;            // row[i], row[jj] (masked k's)
    if (active) {
        #pragma unroll
        for (int u = 0; u < 12; ++u) r[u] = __ldg(&g4[u]);
        if (i  >= kb && i  < kb + QLEN) vi = __ldg(&grow[i]);
        if (jj >= kb && jj < kb + QLEN) vj = __ldg(&grow[jj]);
    } else {
        #pragma unroll
        for (int u = 0; u < 12; ++u) r[u] = make_float4(0.f, 0.f, 0.f, 0.f);
    }

    // ---- sig0 = sigmoid(span) ----
    float span_j = 0.0f, s0 = 0.5f;
    if (tid < NDIM) {
        span_j = s_span[(size_t)bi * NDIM + tid];
        s0 = sigmoidf_(span_j);
        sigA[tid] = s0;
    }
    __syncthreads();

    const float4* sA4 = reinterpret_cast<const float4*>(sigA + kb);
    const float4* sB4 = reinterpret_cast<const float4*>(sigB + kb);

    float q_j = span_j;                    // valid for tid < NDIM

    #pragma unroll
    for (int it = 0; it < 3; ++it) {
        const float4* s4 = (it & 1) ? sB4 : sA4;
        const float*  sg = (it & 1) ? sigB : sigA;

        float a0 = 0.f, a1 = 0.f, a2 = 0.f, a3 = 0.f;
        #pragma unroll
        for (int u = 0; u < 12; ++u) {
            float4 s = s4[u];
            a0 += r[u].x * s.x; a1 += r[u].y * s.y;
            a2 += r[u].z * s.z; a3 += r[u].w * s.w;
        }
        float acc = (a0 + a1) + (a2 + a3);
        acc -= sg[i] * vi + sg[jj] * vj;   // remove k==i, k==j terms
        partial[tid] = acc;
        __syncthreads();

        if (tid < NDIM) {
            if (tid > i)
                q_j = span_j + partial[tid] + partial[tid + NDIM]
                             + partial[tid + 2 * NDIM] + partial[tid + 3 * NDIM];
            float sgn = sigmoidf_(q_j);
            if (it == 2) {
                out[(size_t)bi * NDIM + tid] = sgn;   // final marginals
            } else {
                ((it & 1) ? sigA : sigB)[tid] = sgn;  // next buffer
            }
        }
        __syncthreads();
    }
}

extern "C" void kernel_launch(void* const* d_in, const int* in_sizes, int n_in,
                              void* d_out, int out_size)
{
    (void)in_sizes; (void)n_in; (void)out_size;
    const float* s_span = (const float*)d_in[0];
    const float* s_pair = (const float*)d_in[1];
    // d_in[2] = mask: analytic (strict upper triangle), not needed.
    float* out = (float*)d_out;

    const int grid = 8 * NDIM;             // one CTA per (b,i) = 1536
    mfvi_kernel<<<grid, THREADS>>>(s_span, s_pair, out);
}

// round 7
// speedup vs baseline: 1.3064x; 1.3064x over previous
#include <cuda_runtime.h>

// ConstituencyMFVI: B=8, N=192, 3 iterations.
// PERSISTENT kernel: grid = #SMs, each CTA round-robins over (b,i) tiles.
// Per tile: rows j>i staged gmem->SMEM via coalesced cp.async (4 chunks of
// 48 rows, pad 196), consumed ONCE into registers with iteration-1 FMA fused
// into the LDS pass. Iterations 2-3 run from registers (thread (jj,qd) owns
// row jj, k-quarter qd = 48 floats). Next tile's cp.async issued before
// iterations 2-3 -> DRAM busy across tile boundaries.
// Mask terms k==i, k==j corrected analytically (vi, vj captured in the pass).

#define NDIM    192
#define RPAD    196        // padded row: 16B-aligned, conflict-free LDS.128
#define CHROWS  48
#define THREADS 768
#define NTILES  (8 * NDIM) // 1536

static const int CHUNK_FLOATS = CHROWS * RPAD;                       // 9408
static const int SMEM_BYTES   = (4 * CHUNK_FLOATS + 2 * NDIM + THREADS) * 4;

__device__ __forceinline__ unsigned smem_u32(const void* p) {
    return (unsigned)__cvta_generic_to_shared(p);
}
__device__ __forceinline__ float sigmoidf_(float x) {
    return 1.0f / (1.0f + __expf(-x));
}

// Issue the 4 cp.async chunk groups for tile g (always commits exactly 4
// groups, empty ones if g is out of range or chunk has no rows).
__device__ __forceinline__ void issue_tile(const float* __restrict__ s_pair,
                                           int g, int tid, float* buf)
{
    const bool valid = (g < NTILES);
    const int  i = valid ? (g % NDIM) : (NDIM - 1);
    const int  rowStart = i + 1;
    const int  nRows    = NDIM - rowStart;
    const float* gbase  = s_pair + (size_t)g * (NDIM * NDIM);

    #pragma unroll
    for (int c = 0; c < 4; ++c) {
        int r0 = c * CHROWS;
        int r1 = r0 + CHROWS; if (r1 > nRows) r1 = nRows;
        if (valid && r1 > r0) {
            int nf4 = (r1 - r0) * (NDIM / 4);
            for (int idx = tid; idx < nf4; idx += THREADS) {
                int rr  = idx / (NDIM / 4);
                int col = (idx % (NDIM / 4)) * 4;
                const float* src = gbase + (size_t)(rowStart + r0 + rr) * NDIM + col;
                unsigned dst = smem_u32(buf + c * CHUNK_FLOATS + rr * RPAD + col);
                asm volatile("cp.async.cg.shared.global [%0], [%1], 16;"
                             :: "r"(dst), "l"(src));
            }
        }
        asm volatile("cp.async.commit_group;");
    }
}

__global__ void __launch_bounds__(THREADS, 1)
mfvi_kernel(const float* __restrict__ s_span,
            const float* __restrict__ s_pair,
            float* __restrict__ out)
{
    extern __shared__ float smem[];
    float* buf     = smem;                       // 4 chunks [48][196]
    float* sigA    = smem + 4 * CHUNK_FLOATS;    // [192]
    float* sigB    = sigA + NDIM;                // [192]
    float* partial = sigB + NDIM;                // [768]

    const int tid = threadIdx.x;
    const int jj  = tid % NDIM;          // row owned by this thread
    const int qd  = tid / NDIM;          // k-quarter
    const int kb  = qd * 48;
    const int stride = gridDim.x;

    // Prologue: start loading this CTA's first tile.
    issue_tile(s_pair, blockIdx.x, tid, buf);

    for (int g = blockIdx.x; g < NTILES; g += stride) {
        const int i        = g % NDIM;
        const int rowStart = i + 1;
        const int lr       = jj - rowStart;      // local row (valid if active)
        const bool active  = (jj > i);

        // sig0 = sigmoid(span); visible to consumers at chunk-0 barrier.
        float span_j = 0.0f;
        if (tid < NDIM) {
            span_j = s_span[(size_t)g * NDIM + tid];
            sigA[tid] = sigmoidf_(span_j);
        }

        // ---- Iteration 1, fused with SMEM->register consume ----
        float4 r[12];
        float vi = 0.0f, vj = 0.0f, acc = 0.0f;
        #pragma unroll
        for (int c = 0; c < 4; ++c) {
            if      (c == 0) asm volatile("cp.async.wait_group 3;");
            else if (c == 1) asm volatile("cp.async.wait_group 2;");
            else if (c == 2) asm volatile("cp.async.wait_group 1;");
            else             asm volatile("cp.async.wait_group 0;");
            __syncthreads();
            if (active && lr >= c * CHROWS && lr < (c + 1) * CHROWS) {
                const float* row = buf + c * CHUNK_FLOATS + (lr - c * CHROWS) * RPAD;
                float a0 = 0.f, a1 = 0.f, a2 = 0.f, a3 = 0.f;
                #pragma unroll
                for (int u = 0; u < 12; ++u) {
                    float4 v = *reinterpret_cast<const float4*>(row + kb + 4 * u);
                    float4 s = *reinterpret_cast<const float4*>(sigA + kb + 4 * u);
                    r[u] = v;
                    a0 += v.x * s.x; a1 += v.y * s.y;
                    a2 += v.z * s.z; a3 += v.w * s.w;
                }
                vi = (i  >= kb && i  < kb + 48) ? row[i]  : 0.0f;
                vj = (jj >= kb && jj < kb + 48) ? row[jj] : 0.0f;
                acc = (a0 + a1) + (a2 + a3) - sigA[i] * vi - sigA[jj] * vj;
            }
        }
        partial[tid] = acc;
        __syncthreads();

        float q_j = span_j;
        if (tid < NDIM) {
            if (tid > i)
                q_j = span_j + partial[tid] + partial[tid + NDIM]
                             + partial[tid + 2 * NDIM] + partial[tid + 3 * NDIM];
            sigB[tid] = sigmoidf_(q_j);
        }
        __syncthreads();

        // Buffers fully consumed -> start loading the NEXT tile now
        // (overlaps iterations 2-3 below).
        issue_tile(s_pair, g + stride, tid, buf);

        // ---- Iteration 2 (reads sigB, writes sigA) ----
        acc = 0.0f;
        if (active) {
            float a0 = 0.f, a1 = 0.f, a2 = 0.f, a3 = 0.f;
            #pragma unroll
            for (int u = 0; u < 12; ++u) {
                float4 s = *reinterpret_cast<const float4*>(sigB + kb + 4 * u);
                a0 += r[u].x * s.x; a1 += r[u].y * s.y;
                a2 += r[u].z * s.z; a3 += r[u].w * s.w;
            }
            acc = (a0 + a1) + (a2 + a3) - sigB[i] * vi - sigB[jj] * vj;
        }
        partial[tid] = acc;
        __syncthreads();
        if (tid < NDIM) {
            if (tid > i)
                q_j = span_j + partial[tid] + partial[tid + NDIM]
                             + partial[tid + 2 * NDIM] + partial[tid + 3 * NDIM];
            sigA[tid] = sigmoidf_(q_j);
        }
        __syncthreads();

        // ---- Iteration 3 (reads sigA) + output ----
        acc = 0.0f;
        if (active) {
            float a0 = 0.f, a1 = 0.f, a2 = 0.f, a3 = 0.f;
            #pragma unroll
            for (int u = 0; u < 12; ++u) {
                float4 s = *reinterpret_cast<const float4*>(sigA + kb + 4 * u);
                a0 += r[u].x * s.x; a1 += r[u].y * s.y;
                a2 += r[u].z * s.z; a3 += r[u].w * s.w;
            }
            acc = (a0 + a1) + (a2 + a3) - sigA[i] * vi - sigA[jj] * vj;
        }
        partial[tid] = acc;
        __syncthreads();
        if (tid < NDIM) {
            if (tid > i)
                q_j = span_j + partial[tid] + partial[tid + NDIM]
                             + partial[tid + 2 * NDIM] + partial[tid + 3 * NDIM];
            out[(size_t)g * NDIM + tid] = sigmoidf_(q_j);
        }
        __syncthreads();   // protect sigA/sigB before next tile overwrites
    }
}

extern "C" void kernel_launch(void* const* d_in, const int* in_sizes, int n_in,
                              void* d_out, int out_size)
{
    (void)in_sizes; (void)n_in; (void)out_size;
    const float* s_span = (const float*)d_in[0];
    const float* s_pair = (const float*)d_in[1];
    // d_in[2] = mask: analytic (strict upper triangle), not needed.
    float* out = (float*)d_out;

    int nsm = 148;
    cudaDeviceGetAttribute(&nsm, cudaDevAttrMultiProcessorCount, 0);
    if (nsm <= 0 || nsm > NTILES) nsm = 148;

    cudaFuncSetAttribute(mfvi_kernel,
                         cudaFuncAttributeMaxDynamicSharedMemorySize, SMEM_BYTES);

    mfvi_kernel<<<nsm, THREADS, SMEM_BYTES>>>(s_span, s_pair, out);
}